// round 5
// baseline (speedup 1.0000x reference)
#include <cuda_runtime.h>
#include <math.h>

// ---------------------------------------------------------------------------
// MS-SSIM, 5 levels, [16,3,512,512] f32.
// u=x+y, v=x-y reformulation; (u,v) and (u^2,v^2) packed into f32x2 pairs so
// every blur FMA is a Blackwell FFMA2 (PTX fma.rn.f32x2) -> 2 flops/instr.
// Separable 11-tap blur in smem; 2x2 pool for next level fused.
// ---------------------------------------------------------------------------

#define NPLANES 48
#define HALO 5
#define TW 32
#define TH 32
#define INW 42
#define INWP 44        // padded row stride (float2 units; 44*8=352 % 16 == 0)
#define INH 42

#define G0 0.001028380f
#define G1 0.007598758f
#define G2 0.036000770f
#define G3 0.109360700f
#define G4 0.213005550f
#define G5 0.266011740f

__device__ __forceinline__ float gw(int k) {
    switch (k) {
        case 0: case 10: return G0;
        case 1: case 9:  return G1;
        case 2: case 8:  return G2;
        case 3: case 7:  return G3;
        case 4: case 6:  return G4;
        default:         return G5;
    }
}

typedef unsigned long long u64;

__device__ __forceinline__ u64 pk2(float lo, float hi) {
    u64 r; asm("mov.b64 %0, {%1, %2};" : "=l"(r) : "f"(lo), "f"(hi)); return r;
}
__device__ __forceinline__ void up2(u64 p, float& lo, float& hi) {
    asm("mov.b64 {%0, %1}, %2;" : "=f"(lo), "=f"(hi) : "l"(p));
}
__device__ __forceinline__ u64 fma2(u64 a, u64 b, u64 c) {
    u64 d; asm("fma.rn.f32x2 %0, %1, %2, %3;" : "=l"(d) : "l"(a), "l"(b), "l"(c)); return d;
}
__device__ __forceinline__ u64 mul2(u64 a, u64 b) {
    u64 d; asm("mul.rn.f32x2 %0, %1, %2;" : "=l"(d) : "l"(a), "l"(b)); return d;
}

#define C1F 0.0001f
#define C2F 0.0009f

__device__ double g_sums[10];

#define OFF_L1 0
#define OFF_L2 3145728
#define OFF_L3 3932160
#define OFF_L4 4128768
#define SCR_TOTAL 4177920
__device__ float g_scr1[SCR_TOTAL];
__device__ float g_scr2[SCR_TOTAL];

__global__ void zero_sums_kernel() {
    if (threadIdx.x < 10) g_sums[threadIdx.x] = 0.0;
}

// One block = 32x32 output tile. blockDim=(32,8)=256.
__global__ void __launch_bounds__(256, 2)
ssim_level_kernel(const float* __restrict__ img1, const float* __restrict__ img2,
                  float* __restrict__ pool1, float* __restrict__ pool2,
                  int H, int W, int level)
{
    __shared__ __align__(16) float2 s_uv[INH * INWP];      // (u,v) pairs
    __shared__ __align__(16) ulonglong2 h4[INH * TW];      // {UV, PQ} packed
    __shared__ float red_s[8], red_c[8];

    const int plane = blockIdx.z;
    const int x0 = blockIdx.x * TW;
    const int y0 = blockIdx.y * TH;
    const float* p1 = img1 + (size_t)plane * H * W;
    const float* p2 = img2 + (size_t)plane * H * W;
    const int tx = threadIdx.x, ty = threadIdx.y;
    const int t  = ty * 32 + tx;

    // packed Gaussian weights (held in regs across both passes)
    u64 W2[11];
    #pragma unroll
    for (int k = 0; k < 11; k++) W2[k] = pk2(gw(k), gw(k));

    // ---- stage (+halo), u=a+b, v=a-b; interior fast path ----
    const bool interior = (x0 >= HALO) && (y0 >= HALO) &&
                          (x0 + TW + HALO <= W) && (y0 + TH + HALO <= H);
    if (interior) {
        #pragma unroll
        for (int idx = t; idx < INH * INW; idx += 256) {
            int r = idx / INW, c = idx - r * INW;
            int gi = (y0 + r - HALO) * W + (x0 + c - HALO);
            float a = __ldg(p1 + gi);
            float b = __ldg(p2 + gi);
            s_uv[r * INWP + c] = make_float2(a + b, a - b);
        }
    } else {
        #pragma unroll
        for (int idx = t; idx < INH * INW; idx += 256) {
            int r = idx / INW, c = idx - r * INW;
            int gy = y0 + r - HALO;
            int gx = x0 + c - HALO;
            float a = 0.f, b = 0.f;
            if (gy >= 0 && gy < H && gx >= 0 && gx < W) {
                int gi = gy * W + gx;
                a = __ldg(p1 + gi);
                b = __ldg(p2 + gi);
            }
            s_uv[r * INWP + c] = make_float2(a + b, a - b);
        }
    }
    __syncthreads();

    // ---- fused 2x2 pool of interior -> 16x16 ----
    if (pool1) {
        int i = t >> 4, j = t & 15;
        int base = (HALO + 2 * i) * INWP + HALO + 2 * j;
        float2 q00 = s_uv[base],        q01 = s_uv[base + 1];
        float2 q10 = s_uv[base + INWP], q11 = s_uv[base + INWP + 1];
        float su = (q00.x + q01.x) + (q10.x + q11.x);
        float sv = (q00.y + q01.y) + (q10.y + q11.y);
        int W2d = W >> 1;
        size_t oi = (size_t)plane * (W2d * (H >> 1)) + ((y0 >> 1) + i) * W2d + (x0 >> 1) + j;
        pool1[oi] = 0.125f * (su + sv);
        pool2[oi] = 0.125f * (su - sv);
    }

    // ---- horizontal pass: 42 rows x 8 groups of 4 cols = 336 tasks ----
    for (int task = t; task < INH * 8; task += 256) {
        int r  = task >> 3;
        int cc = (task & 7) << 2;
        const ulonglong2* pw = (const ulonglong2*)(s_uv + r * INWP + cc);

        u64 uv[14];
        #pragma unroll
        for (int i = 0; i < 7; i++) {
            ulonglong2 q = pw[i];          // LDS.128 = 2 (u,v) pairs
            uv[2 * i]     = q.x;
            uv[2 * i + 1] = q.y;
        }
        u64 sq[14];
        #pragma unroll
        for (int i = 0; i < 14; i++) sq[i] = mul2(uv[i], uv[i]);

        #pragma unroll
        for (int j = 0; j < 4; j++) {
            u64 UV = 0ULL, PQ = 0ULL;      // packed (+0.0f, +0.0f)
            #pragma unroll
            for (int k = 0; k < 11; k++) {
                UV = fma2(W2[k], uv[j + k], UV);
                PQ = fma2(W2[k], sq[j + k], PQ);
            }
            h4[r * TW + cc + j] = make_ulonglong2(UV, PQ);
        }
    }
    __syncthreads();

    // ---- vertical pass: column tx, 4 output rows/thread ----
    const int rbase = ty * 4;
    u64 aUV[4] = {0ULL, 0ULL, 0ULL, 0ULL};
    u64 aPQ[4] = {0ULL, 0ULL, 0ULL, 0ULL};
    #pragma unroll
    for (int k = 0; k < 14; k++) {
        ulonglong2 hv = h4[(rbase + k) * TW + tx];
        #pragma unroll
        for (int j = 0; j < 4; j++) {
            int ki = k - j;
            if (ki >= 0 && ki <= 10) {
                aUV[j] = fma2(W2[ki], hv.x, aUV[j]);
                aPQ[j] = fma2(W2[ki], hv.y, aPQ[j]);
            }
        }
    }

    // ---- epilogue ----
    float lssim = 0.f, lcs = 0.f;
    #pragma unroll
    for (int j = 0; j < 4; j++) {
        float U, V, P, Q;
        up2(aUV[j], U, V);
        up2(aPQ[j], P, Q);
        float A = U * U;
        float B = V * V;
        float num_l = 0.5f * (A - B) + C1F;
        float den_l = 0.5f * (A + B) + C1F;
        float num_c = 0.5f * ((P - Q) - (A - B)) + C2F;
        float den_c = 0.5f * ((P + Q) - (A + B)) + C2F;
        float cs = __fdividef(num_c, den_c);
        lssim += __fdividef(num_l, den_l) * cs;
        lcs   += cs;
    }

    #pragma unroll
    for (int o = 16; o > 0; o >>= 1) {
        lssim += __shfl_xor_sync(0xFFFFFFFFu, lssim, o);
        lcs   += __shfl_xor_sync(0xFFFFFFFFu, lcs,   o);
    }
    if (tx == 0) { red_s[ty] = lssim; red_c[ty] = lcs; }
    __syncthreads();
    if (t == 0) {
        float S = 0.f, Cc = 0.f;
        #pragma unroll
        for (int i = 0; i < 8; i++) { S += red_s[i]; Cc += red_c[i]; }
        atomicAdd(&g_sums[2 * level],     (double)S);
        atomicAdd(&g_sums[2 * level + 1], (double)Cc);
    }
}

__global__ void finalize_kernel(float* __restrict__ out)
{
    const double w[5] = {0.0448, 0.2856, 0.3001, 0.2363, 0.1333};
    double res = 1.0;
    #pragma unroll
    for (int l = 0; l < 5; l++) {
        int side = 512 >> l;
        double cnt = (double)NPLANES * side * side;
        double v = (l < 4) ? (g_sums[2 * l + 1] / cnt)
                           : (g_sums[2 * l] / cnt);
        res *= pow(v, w[l]);
    }
    out[0] = (float)res;
}

extern "C" void kernel_launch(void* const* d_in, const int* in_sizes, int n_in,
                              void* d_out, int out_size)
{
    const float* img1 = (const float*)d_in[0];
    const float* img2 = (const float*)d_in[1];
    float* out = (float*)d_out;

    float *scr1 = nullptr, *scr2 = nullptr;
    cudaGetSymbolAddress((void**)&scr1, g_scr1);
    cudaGetSymbolAddress((void**)&scr2, g_scr2);

    const float* a[5];
    const float* b[5];
    a[0] = img1;            b[0] = img2;
    a[1] = scr1 + OFF_L1;   b[1] = scr2 + OFF_L1;
    a[2] = scr1 + OFF_L2;   b[2] = scr2 + OFF_L2;
    a[3] = scr1 + OFF_L3;   b[3] = scr2 + OFF_L3;
    a[4] = scr1 + OFF_L4;   b[4] = scr2 + OFF_L4;

    zero_sums_kernel<<<1, 32>>>();

    dim3 blk(32, 8);
    for (int l = 0; l < 5; l++) {
        int side = 512 >> l;
        dim3 grd(side / TW, side / TH, NPLANES);
        float* n1 = (l < 4) ? (float*)a[l + 1] : nullptr;
        float* n2 = (l < 4) ? (float*)b[l + 1] : nullptr;
        ssim_level_kernel<<<grd, blk>>>(a[l], b[l], n1, n2, side, side, l);
    }
    finalize_kernel<<<1, 1>>>(out);
}

// round 6
// speedup vs baseline: 1.2357x; 1.2357x over previous
#include <cuda_runtime.h>
#include <math.h>

// ---------------------------------------------------------------------------
// MS-SSIM, 5 levels, [16,3,512,512] f32.
// u=x+y, v=x-y reformulation (4 blurred fields: U,V,UU,VV).
// Separable 11-tap blur; BOTH passes k-outer / accumulator-inner so the live
// register set stays small (16 acc + current window element).
// 384-thread blocks, <=1 h-task per thread, launch_bounds(384,4) for occupancy.
// Scalar fmaf with literal weights -> FFMA-imm (rt_SMSP=1).
// 2x2 pool for next level fused.
// ---------------------------------------------------------------------------

#define NPLANES 48
#define HALO 5
#define TW 32
#define TH 32
#define INW 42
#define INWP 44        // float2 units; row base 44*8B is 16B-aligned
#define INH 42
#define NTHREADS 384

#define G0 0.001028380f
#define G1 0.007598758f
#define G2 0.036000770f
#define G3 0.109360700f
#define G4 0.213005550f
#define G5 0.266011740f

__device__ __forceinline__ float gw(int k) {
    switch (k) {
        case 0: case 10: return G0;
        case 1: case 9:  return G1;
        case 2: case 8:  return G2;
        case 3: case 7:  return G3;
        case 4: case 6:  return G4;
        default:         return G5;
    }
}

#define C1F 0.0001f
#define C2F 0.0009f

__device__ double g_sums[10];

#define OFF_L1 0
#define OFF_L2 3145728
#define OFF_L3 3932160
#define OFF_L4 4128768
#define SCR_TOTAL 4177920
__device__ float g_scr1[SCR_TOTAL];
__device__ float g_scr2[SCR_TOTAL];

__global__ void zero_sums_kernel() {
    if (threadIdx.x < 10) g_sums[threadIdx.x] = 0.0;
}

// One block = 32x32 output tile. blockDim = 384 (flat).
__global__ void __launch_bounds__(NTHREADS, 4)
ssim_level_kernel(const float* __restrict__ img1, const float* __restrict__ img2,
                  float* __restrict__ pool1, float* __restrict__ pool2,
                  int H, int W, int level)
{
    __shared__ __align__(16) float2 s_uv[INH * INWP];  // (u,v) pairs, 14.8KB
    __shared__ __align__(16) float4 h4[INH * TW];      // {U,V,P,Q}, 21.5KB
    __shared__ float red_s[8], red_c[8];

    const int plane = blockIdx.z;
    const int x0 = blockIdx.x * TW;
    const int y0 = blockIdx.y * TH;
    const float* p1 = img1 + (size_t)plane * H * W;
    const float* p2 = img2 + (size_t)plane * H * W;
    const int t = threadIdx.x;

    // ---- stage (+halo), u=a+b, v=a-b; interior fast path ----
    const bool interior = (x0 >= HALO) && (y0 >= HALO) &&
                          (x0 + TW + HALO <= W) && (y0 + TH + HALO <= H);
    if (interior) {
        #pragma unroll
        for (int i = 0; i < 5; i++) {
            int idx = t + i * NTHREADS;
            if (idx < INH * INW) {
                int r = idx / INW, c = idx - r * INW;
                int gi = (y0 + r - HALO) * W + (x0 + c - HALO);
                float a = __ldg(p1 + gi);
                float b = __ldg(p2 + gi);
                s_uv[r * INWP + c] = make_float2(a + b, a - b);
            }
        }
    } else {
        #pragma unroll
        for (int i = 0; i < 5; i++) {
            int idx = t + i * NTHREADS;
            if (idx < INH * INW) {
                int r = idx / INW, c = idx - r * INW;
                int gy = y0 + r - HALO;
                int gx = x0 + c - HALO;
                float a = 0.f, b = 0.f;
                if (gy >= 0 && gy < H && gx >= 0 && gx < W) {
                    int gi = gy * W + gx;
                    a = __ldg(p1 + gi);
                    b = __ldg(p2 + gi);
                }
                s_uv[r * INWP + c] = make_float2(a + b, a - b);
            }
        }
    }
    __syncthreads();

    // ---- fused 2x2 pool of interior -> 16x16 (threads 0..255) ----
    if (pool1 && t < 256) {
        int i = t >> 4, j = t & 15;
        int base = (HALO + 2 * i) * INWP + HALO + 2 * j;
        float2 q00 = s_uv[base],        q01 = s_uv[base + 1];
        float2 q10 = s_uv[base + INWP], q11 = s_uv[base + INWP + 1];
        float su = (q00.x + q01.x) + (q10.x + q11.x);
        float sv = (q00.y + q01.y) + (q10.y + q11.y);
        int W2 = W >> 1;
        size_t oi = (size_t)plane * (W2 * (H >> 1)) + ((y0 >> 1) + i) * W2 + (x0 >> 1) + j;
        pool1[oi] = 0.125f * (su + sv);
        pool2[oi] = 0.125f * (su - sv);
    }

    // ---- horizontal pass: 42 rows x 8 groups of 4 cols = 336 tasks,
    //      one per thread; k-outer, 16 accumulators ----
    if (t < INH * 8) {
        const int r  = t >> 3;
        const int cc = (t & 7) << 2;
        const float4* pw = (const float4*)(s_uv + r * INWP + cc);

        float aU[4] = {0,0,0,0}, aV[4] = {0,0,0,0};
        float aP[4] = {0,0,0,0}, aQ[4] = {0,0,0,0};

        #pragma unroll
        for (int kk = 0; kk < 7; kk++) {
            float4 q = pw[kk];                 // two (u,v) pairs
            #pragma unroll
            for (int h = 0; h < 2; h++) {
                const int k = 2 * kk + h;
                float u = h ? q.z : q.x;
                float v = h ? q.w : q.y;
                float uu = u * u;
                float vv = v * v;
                #pragma unroll
                for (int j = 0; j < 4; j++) {
                    const int ki = k - j;
                    if (ki >= 0 && ki <= 10) {
                        const float w = gw(ki);
                        aU[j] = fmaf(w, u,  aU[j]);
                        aV[j] = fmaf(w, v,  aV[j]);
                        aP[j] = fmaf(w, uu, aP[j]);
                        aQ[j] = fmaf(w, vv, aQ[j]);
                    }
                }
            }
        }
        #pragma unroll
        for (int j = 0; j < 4; j++)
            h4[r * TW + cc + j] = make_float4(aU[j], aV[j], aP[j], aQ[j]);
    }
    __syncthreads();

    // ---- vertical pass + epilogue: threads 0..255, 4 output rows each ----
    float lssim = 0.f, lcs = 0.f;
    if (t < 256) {
        const int tx = t & 31;
        const int rbase = (t >> 5) * 4;

        float aU[4] = {0,0,0,0}, aV[4] = {0,0,0,0};
        float aP[4] = {0,0,0,0}, aQ[4] = {0,0,0,0};
        #pragma unroll
        for (int k = 0; k < 14; k++) {
            float4 hv = h4[(rbase + k) * TW + tx];
            #pragma unroll
            for (int j = 0; j < 4; j++) {
                const int ki = k - j;
                if (ki >= 0 && ki <= 10) {
                    const float w = gw(ki);
                    aU[j] = fmaf(w, hv.x, aU[j]);
                    aV[j] = fmaf(w, hv.y, aV[j]);
                    aP[j] = fmaf(w, hv.z, aP[j]);
                    aQ[j] = fmaf(w, hv.w, aQ[j]);
                }
            }
        }

        #pragma unroll
        for (int j = 0; j < 4; j++) {
            float A = aU[j] * aU[j];
            float B = aV[j] * aV[j];
            float P = aP[j], Q = aQ[j];
            float num_l = 0.5f * (A - B) + C1F;
            float den_l = 0.5f * (A + B) + C1F;
            float num_c = 0.5f * ((P - Q) - (A - B)) + C2F;
            float den_c = 0.5f * ((P + Q) - (A + B)) + C2F;
            float cs = __fdividef(num_c, den_c);
            lssim += __fdividef(num_l, den_l) * cs;
            lcs   += cs;
        }

        #pragma unroll
        for (int o = 16; o > 0; o >>= 1) {
            lssim += __shfl_xor_sync(0xFFFFFFFFu, lssim, o);
            lcs   += __shfl_xor_sync(0xFFFFFFFFu, lcs,   o);
        }
        if (tx == 0) { red_s[t >> 5] = lssim; red_c[t >> 5] = lcs; }
    }
    __syncthreads();
    if (t == 0) {
        float S = 0.f, Cc = 0.f;
        #pragma unroll
        for (int i = 0; i < 8; i++) { S += red_s[i]; Cc += red_c[i]; }
        atomicAdd(&g_sums[2 * level],     (double)S);
        atomicAdd(&g_sums[2 * level + 1], (double)Cc);
    }
}

__global__ void finalize_kernel(float* __restrict__ out)
{
    const double w[5] = {0.0448, 0.2856, 0.3001, 0.2363, 0.1333};
    double res = 1.0;
    #pragma unroll
    for (int l = 0; l < 5; l++) {
        int side = 512 >> l;
        double cnt = (double)NPLANES * side * side;
        double v = (l < 4) ? (g_sums[2 * l + 1] / cnt)
                           : (g_sums[2 * l] / cnt);
        res *= pow(v, w[l]);
    }
    out[0] = (float)res;
}

extern "C" void kernel_launch(void* const* d_in, const int* in_sizes, int n_in,
                              void* d_out, int out_size)
{
    const float* img1 = (const float*)d_in[0];
    const float* img2 = (const float*)d_in[1];
    float* out = (float*)d_out;

    float *scr1 = nullptr, *scr2 = nullptr;
    cudaGetSymbolAddress((void**)&scr1, g_scr1);
    cudaGetSymbolAddress((void**)&scr2, g_scr2);

    const float* a[5];
    const float* b[5];
    a[0] = img1;            b[0] = img2;
    a[1] = scr1 + OFF_L1;   b[1] = scr2 + OFF_L1;
    a[2] = scr1 + OFF_L2;   b[2] = scr2 + OFF_L2;
    a[3] = scr1 + OFF_L3;   b[3] = scr2 + OFF_L3;
    a[4] = scr1 + OFF_L4;   b[4] = scr2 + OFF_L4;

    zero_sums_kernel<<<1, 32>>>();

    for (int l = 0; l < 5; l++) {
        int side = 512 >> l;
        dim3 grd(side / TW, side / TH, NPLANES);
        float* n1 = (l < 4) ? (float*)a[l + 1] : nullptr;
        float* n2 = (l < 4) ? (float*)b[l + 1] : nullptr;
        ssim_level_kernel<<<grd, NTHREADS>>>(a[l], b[l], n1, n2, side, side, l);
    }
    finalize_kernel<<<1, 1>>>(out);
}

// round 7
// speedup vs baseline: 1.3568x; 1.0980x over previous
#include <cuda_runtime.h>
#include <math.h>

// ---------------------------------------------------------------------------
// MS-SSIM, 5 levels, [16,3,512,512] f32.
// u=x+y, v=x-y reformulation (4 blurred fields: U,V,UU,VV).
// Separable 11-tap blur, k-outer both passes, 384-thread blocks.
// R7: XOR bank swizzles on s_uv (16B granules) and h4 (column ^ col>>2)
// eliminate the 2-way h-pass load conflicts and 4-way h4 store conflicts.
// 2x2 pool for next level fused.
// ---------------------------------------------------------------------------

#define NPLANES 48
#define HALO 5
#define TW 32
#define TH 32
#define INW 42
#define INWP 44        // float2 units per row (352B, 16B-aligned)
#define INH 42
#define NTHREADS 384

#define G0 0.001028380f
#define G1 0.007598758f
#define G2 0.036000770f
#define G3 0.109360700f
#define G4 0.213005550f
#define G5 0.266011740f

__device__ __forceinline__ float gw(int k) {
    switch (k) {
        case 0: case 10: return G0;
        case 1: case 9:  return G1;
        case 2: case 8:  return G2;
        case 3: case 7:  return G3;
        case 4: case 6:  return G4;
        default:         return G5;
    }
}

// 16B-granule swizzle within an s_uv row (granule = 2 float2)
__device__ __forceinline__ int swzg(int g) { return g ^ ((g >> 3) & 1); }
// s_uv float2 index for logical (r, c)
__device__ __forceinline__ int suv_idx(int r, int c) {
    int g = swzg(c >> 1);
    return r * INWP + (g << 1) + (c & 1);
}
// h4 column swizzle (bijective on 0..31)
__device__ __forceinline__ int swzc(int col) { return col ^ (col >> 2); }

#define C1F 0.0001f
#define C2F 0.0009f

__device__ double g_sums[10];

#define OFF_L1 0
#define OFF_L2 3145728
#define OFF_L3 3932160
#define OFF_L4 4128768
#define SCR_TOTAL 4177920
__device__ float g_scr1[SCR_TOTAL];
__device__ float g_scr2[SCR_TOTAL];

__global__ void zero_sums_kernel() {
    if (threadIdx.x < 10) g_sums[threadIdx.x] = 0.0;
}

// One block = 32x32 output tile. blockDim = 384 (flat).
__global__ void __launch_bounds__(NTHREADS, 4)
ssim_level_kernel(const float* __restrict__ img1, const float* __restrict__ img2,
                  float* __restrict__ pool1, float* __restrict__ pool2,
                  int H, int W, int level)
{
    __shared__ __align__(16) float2 s_uv[INH * INWP];  // swizzled (u,v)
    __shared__ __align__(16) float4 h4[INH * TW];      // swizzled cols {U,V,P,Q}
    __shared__ float red_s[8], red_c[8];

    const int plane = blockIdx.z;
    const int x0 = blockIdx.x * TW;
    const int y0 = blockIdx.y * TH;
    const float* p1 = img1 + (size_t)plane * H * W;
    const float* p2 = img2 + (size_t)plane * H * W;
    const int t = threadIdx.x;

    // ---- stage (+halo), u=a+b, v=a-b; interior fast path ----
    const bool interior = (x0 >= HALO) && (y0 >= HALO) &&
                          (x0 + TW + HALO <= W) && (y0 + TH + HALO <= H);
    if (interior) {
        #pragma unroll
        for (int i = 0; i < 5; i++) {
            int idx = t + i * NTHREADS;
            if (idx < INH * INW) {
                int r = idx / INW, c = idx - r * INW;
                int gi = (y0 + r - HALO) * W + (x0 + c - HALO);
                float a = __ldg(p1 + gi);
                float b = __ldg(p2 + gi);
                s_uv[suv_idx(r, c)] = make_float2(a + b, a - b);
            }
        }
    } else {
        #pragma unroll
        for (int i = 0; i < 5; i++) {
            int idx = t + i * NTHREADS;
            if (idx < INH * INW) {
                int r = idx / INW, c = idx - r * INW;
                int gy = y0 + r - HALO;
                int gx = x0 + c - HALO;
                float a = 0.f, b = 0.f;
                if (gy >= 0 && gy < H && gx >= 0 && gx < W) {
                    int gi = gy * W + gx;
                    a = __ldg(p1 + gi);
                    b = __ldg(p2 + gi);
                }
                s_uv[suv_idx(r, c)] = make_float2(a + b, a - b);
            }
        }
    }
    __syncthreads();

    // ---- fused 2x2 pool of interior -> 16x16 (threads 0..255) ----
    if (pool1 && t < 256) {
        int i = t >> 4, j = t & 15;
        int r0 = HALO + 2 * i, c0 = HALO + 2 * j;
        float2 q00 = s_uv[suv_idx(r0, c0)];
        float2 q01 = s_uv[suv_idx(r0, c0 + 1)];
        float2 q10 = s_uv[suv_idx(r0 + 1, c0)];
        float2 q11 = s_uv[suv_idx(r0 + 1, c0 + 1)];
        float su = (q00.x + q01.x) + (q10.x + q11.x);
        float sv = (q00.y + q01.y) + (q10.y + q11.y);
        int W2 = W >> 1;
        size_t oi = (size_t)plane * (W2 * (H >> 1)) + ((y0 >> 1) + i) * W2 + (x0 >> 1) + j;
        pool1[oi] = 0.125f * (su + sv);
        pool2[oi] = 0.125f * (su - sv);
    }

    // ---- horizontal pass: 42 rows x 8 groups of 4 cols = 336 tasks ----
    if (t < INH * 8) {
        const int r     = t >> 3;
        const int jgrp  = t & 7;
        const int cc    = jgrp << 2;      // first output col of this group
        const int gbase = jgrp << 1;      // first 16B granule of window
        const float4* s_uv4 = (const float4*)s_uv;
        const int rowb = r * (INWP >> 1); // float4 units per row = 22

        float aU[4] = {0,0,0,0}, aV[4] = {0,0,0,0};
        float aP[4] = {0,0,0,0}, aQ[4] = {0,0,0,0};

        #pragma unroll
        for (int kk = 0; kk < 7; kk++) {
            float4 q = s_uv4[rowb + swzg(gbase + kk)];   // two (u,v) pairs
            #pragma unroll
            for (int h = 0; h < 2; h++) {
                const int k = 2 * kk + h;
                float u = h ? q.z : q.x;
                float v = h ? q.w : q.y;
                float uu = u * u;
                float vv = v * v;
                #pragma unroll
                for (int j = 0; j < 4; j++) {
                    const int ki = k - j;
                    if (ki >= 0 && ki <= 10) {
                        const float w = gw(ki);
                        aU[j] = fmaf(w, u,  aU[j]);
                        aV[j] = fmaf(w, v,  aV[j]);
                        aP[j] = fmaf(w, uu, aP[j]);
                        aQ[j] = fmaf(w, vv, aQ[j]);
                    }
                }
            }
        }
        const int ccs = cc >> 2;  // = jgrp; (cc+jj)>>2 == ccs since jj<4
        #pragma unroll
        for (int j = 0; j < 4; j++)
            h4[r * TW + ((cc + j) ^ ccs)] = make_float4(aU[j], aV[j], aP[j], aQ[j]);
    }
    __syncthreads();

    // ---- vertical pass + epilogue: threads 0..255, 4 output rows each ----
    float lssim = 0.f, lcs = 0.f;
    if (t < 256) {
        const int tx  = t & 31;
        const int txs = swzc(tx);
        const int rbase = (t >> 5) * 4;

        float aU[4] = {0,0,0,0}, aV[4] = {0,0,0,0};
        float aP[4] = {0,0,0,0}, aQ[4] = {0,0,0,0};
        #pragma unroll
        for (int k = 0; k < 14; k++) {
            float4 hv = h4[(rbase + k) * TW + txs];
            #pragma unroll
            for (int j = 0; j < 4; j++) {
                const int ki = k - j;
                if (ki >= 0 && ki <= 10) {
                    const float w = gw(ki);
                    aU[j] = fmaf(w, hv.x, aU[j]);
                    aV[j] = fmaf(w, hv.y, aV[j]);
                    aP[j] = fmaf(w, hv.z, aP[j]);
                    aQ[j] = fmaf(w, hv.w, aQ[j]);
                }
            }
        }

        #pragma unroll
        for (int j = 0; j < 4; j++) {
            float A = aU[j] * aU[j];
            float B = aV[j] * aV[j];
            float P = aP[j], Q = aQ[j];
            float num_l = 0.5f * (A - B) + C1F;
            float den_l = 0.5f * (A + B) + C1F;
            float num_c = 0.5f * ((P - Q) - (A - B)) + C2F;
            float den_c = 0.5f * ((P + Q) - (A + B)) + C2F;
            float cs = __fdividef(num_c, den_c);
            lssim += __fdividef(num_l, den_l) * cs;
            lcs   += cs;
        }

        #pragma unroll
        for (int o = 16; o > 0; o >>= 1) {
            lssim += __shfl_xor_sync(0xFFFFFFFFu, lssim, o);
            lcs   += __shfl_xor_sync(0xFFFFFFFFu, lcs,   o);
        }
        if (tx == 0) { red_s[t >> 5] = lssim; red_c[t >> 5] = lcs; }
    }
    __syncthreads();
    if (t == 0) {
        float S = 0.f, Cc = 0.f;
        #pragma unroll
        for (int i = 0; i < 8; i++) { S += red_s[i]; Cc += red_c[i]; }
        atomicAdd(&g_sums[2 * level],     (double)S);
        atomicAdd(&g_sums[2 * level + 1], (double)Cc);
    }
}

__global__ void finalize_kernel(float* __restrict__ out)
{
    const double w[5] = {0.0448, 0.2856, 0.3001, 0.2363, 0.1333};
    double res = 1.0;
    #pragma unroll
    for (int l = 0; l < 5; l++) {
        int side = 512 >> l;
        double cnt = (double)NPLANES * side * side;
        double v = (l < 4) ? (g_sums[2 * l + 1] / cnt)
                           : (g_sums[2 * l] / cnt);
        res *= pow(v, w[l]);
    }
    out[0] = (float)res;
}

extern "C" void kernel_launch(void* const* d_in, const int* in_sizes, int n_in,
                              void* d_out, int out_size)
{
    const float* img1 = (const float*)d_in[0];
    const float* img2 = (const float*)d_in[1];
    float* out = (float*)d_out;

    float *scr1 = nullptr, *scr2 = nullptr;
    cudaGetSymbolAddress((void**)&scr1, g_scr1);
    cudaGetSymbolAddress((void**)&scr2, g_scr2);

    const float* a[5];
    const float* b[5];
    a[0] = img1;            b[0] = img2;
    a[1] = scr1 + OFF_L1;   b[1] = scr2 + OFF_L1;
    a[2] = scr1 + OFF_L2;   b[2] = scr2 + OFF_L2;
    a[3] = scr1 + OFF_L3;   b[3] = scr2 + OFF_L3;
    a[4] = scr1 + OFF_L4;   b[4] = scr2 + OFF_L4;

    zero_sums_kernel<<<1, 32>>>();

    for (int l = 0; l < 5; l++) {
        int side = 512 >> l;
        dim3 grd(side / TW, side / TH, NPLANES);
        float* n1 = (l < 4) ? (float*)a[l + 1] : nullptr;
        float* n2 = (l < 4) ? (float*)b[l + 1] : nullptr;
        ssim_level_kernel<<<grd, NTHREADS>>>(a[l], b[l], n1, n2, side, side, l);
    }
    finalize_kernel<<<1, 1>>>(out);
}

// round 8
// speedup vs baseline: 1.3804x; 1.0174x over previous
#include <cuda_runtime.h>
#include <math.h>

// ---------------------------------------------------------------------------
// MS-SSIM, 5 levels, [16,3,512,512] f32.
// u=x+y, v=x-y reformulation (4 blurred fields U,V,UU,VV), separable 11-tap
// blur, k-outer both passes, XOR bank swizzles (R7).
// R8: templated tile height. Big levels (512/256/128): 64x32 tiles, 512 thr,
// dynamic smem (64KB), 3 blocks/SM -> 75% occ, -12% halo overcompute, v-pass
// and pool use ALL threads. Small levels (64/32): 32x32 tiles, 384 thr.
// ---------------------------------------------------------------------------

#define NPLANES 48
#define HALO 5
#define TW 32
#define INW 42
#define INWP 44        // float2 units per row (352B)

#define G0 0.001028380f
#define G1 0.007598758f
#define G2 0.036000770f
#define G3 0.109360700f
#define G4 0.213005550f
#define G5 0.266011740f

__device__ __forceinline__ float gw(int k) {
    switch (k) {
        case 0: case 10: return G0;
        case 1: case 9:  return G1;
        case 2: case 8:  return G2;
        case 3: case 7:  return G3;
        case 4: case 6:  return G4;
        default:         return G5;
    }
}

// 16B-granule swizzle within an s_uv row
__device__ __forceinline__ int swzg(int g) { return g ^ ((g >> 3) & 1); }
__device__ __forceinline__ int suv_idx(int r, int c) {
    int g = swzg(c >> 1);
    return r * INWP + (g << 1) + (c & 1);
}
__device__ __forceinline__ int swzc(int col) { return col ^ (col >> 2); }

#define C1F 0.0001f
#define C2F 0.0009f

__device__ double g_sums[10];

#define OFF_L1 0
#define OFF_L2 3145728
#define OFF_L3 3932160
#define OFF_L4 4128768
#define SCR_TOTAL 4177920
__device__ float g_scr1[SCR_TOTAL];
__device__ float g_scr2[SCR_TOTAL];

__global__ void zero_sums_kernel() {
    if (threadIdx.x < 10) g_sums[threadIdx.x] = 0.0;
}

// One block = TH x 32 output tile. NT threads. Dynamic smem:
//   s_uv: (TH+10)*INWP float2   then   h4: (TH+10)*TW float4
template<int TH, int NT, int MINBLK>
__global__ void __launch_bounds__(NT, MINBLK)
ssim_level_kernel(const float* __restrict__ img1, const float* __restrict__ img2,
                  float* __restrict__ pool1, float* __restrict__ pool2,
                  int H, int W, int level)
{
    constexpr int INH = TH + 10;
    extern __shared__ __align__(16) char smem_dyn[];
    float2* s_uv = (float2*)smem_dyn;                              // INH*INWP
    float4* h4   = (float4*)(smem_dyn + INH * INWP * sizeof(float2)); // INH*TW
    __shared__ float red_s[NT / 32], red_c[NT / 32];

    const int plane = blockIdx.z;
    const int x0 = blockIdx.x * TW;
    const int y0 = blockIdx.y * TH;
    const float* p1 = img1 + (size_t)plane * H * W;
    const float* p2 = img2 + (size_t)plane * H * W;
    const int t = threadIdx.x;

    // ---- stage (+halo), u=a+b, v=a-b; interior fast path ----
    const bool interior = (x0 >= HALO) && (y0 >= HALO) &&
                          (x0 + TW + HALO <= W) && (y0 + TH + HALO <= H);
    if (interior) {
        #pragma unroll
        for (int idx = t; idx < INH * INW; idx += NT) {
            int r = idx / INW, c = idx - r * INW;
            int gi = (y0 + r - HALO) * W + (x0 + c - HALO);
            float a = __ldg(p1 + gi);
            float b = __ldg(p2 + gi);
            s_uv[suv_idx(r, c)] = make_float2(a + b, a - b);
        }
    } else {
        #pragma unroll
        for (int idx = t; idx < INH * INW; idx += NT) {
            int r = idx / INW, c = idx - r * INW;
            int gy = y0 + r - HALO;
            int gx = x0 + c - HALO;
            float a = 0.f, b = 0.f;
            if (gy >= 0 && gy < H && gx >= 0 && gx < W) {
                int gi = gy * W + gx;
                a = __ldg(p1 + gi);
                b = __ldg(p2 + gi);
            }
            s_uv[suv_idx(r, c)] = make_float2(a + b, a - b);
        }
    }
    __syncthreads();

    // ---- fused 2x2 pool of interior (TH x 32 -> TH/2 x 16) ----
    if (pool1 && t < TH * 8) {
        int i = t >> 4, j = t & 15;
        int r0 = HALO + 2 * i, c0 = HALO + 2 * j;
        float2 q00 = s_uv[suv_idx(r0, c0)];
        float2 q01 = s_uv[suv_idx(r0, c0 + 1)];
        float2 q10 = s_uv[suv_idx(r0 + 1, c0)];
        float2 q11 = s_uv[suv_idx(r0 + 1, c0 + 1)];
        float su = (q00.x + q01.x) + (q10.x + q11.x);
        float sv = (q00.y + q01.y) + (q10.y + q11.y);
        int W2 = W >> 1;
        size_t oi = (size_t)plane * (W2 * (H >> 1)) + ((y0 >> 1) + i) * W2 + (x0 >> 1) + j;
        pool1[oi] = 0.125f * (su + sv);
        pool2[oi] = 0.125f * (su - sv);
    }

    // ---- horizontal pass: INH rows x 8 groups of 4 cols ----
    for (int task = t; task < INH * 8; task += NT) {
        const int r     = task >> 3;
        const int jgrp  = task & 7;
        const int cc    = jgrp << 2;
        const int gbase = jgrp << 1;
        const float4* s_uv4 = (const float4*)s_uv;
        const int rowb = r * (INWP >> 1);

        float aU[4] = {0,0,0,0}, aV[4] = {0,0,0,0};
        float aP[4] = {0,0,0,0}, aQ[4] = {0,0,0,0};

        #pragma unroll
        for (int kk = 0; kk < 7; kk++) {
            float4 q = s_uv4[rowb + swzg(gbase + kk)];
            #pragma unroll
            for (int h = 0; h < 2; h++) {
                const int k = 2 * kk + h;
                float u = h ? q.z : q.x;
                float v = h ? q.w : q.y;
                float uu = u * u;
                float vv = v * v;
                #pragma unroll
                for (int j = 0; j < 4; j++) {
                    const int ki = k - j;
                    if (ki >= 0 && ki <= 10) {
                        const float w = gw(ki);
                        aU[j] = fmaf(w, u,  aU[j]);
                        aV[j] = fmaf(w, v,  aV[j]);
                        aP[j] = fmaf(w, uu, aP[j]);
                        aQ[j] = fmaf(w, vv, aQ[j]);
                    }
                }
            }
        }
        #pragma unroll
        for (int j = 0; j < 4; j++)
            h4[r * TW + ((cc + j) ^ jgrp)] = make_float4(aU[j], aV[j], aP[j], aQ[j]);
    }
    __syncthreads();

    // ---- vertical pass + epilogue: TH*8 tasks (4 output rows each) ----
    float lssim = 0.f, lcs = 0.f;
    if (t < TH * 8) {
        const int tx  = t & 31;
        const int txs = swzc(tx);
        const int rbase = (t >> 5) * 4;

        float aU[4] = {0,0,0,0}, aV[4] = {0,0,0,0};
        float aP[4] = {0,0,0,0}, aQ[4] = {0,0,0,0};
        #pragma unroll
        for (int k = 0; k < 14; k++) {
            float4 hv = h4[(rbase + k) * TW + txs];
            #pragma unroll
            for (int j = 0; j < 4; j++) {
                const int ki = k - j;
                if (ki >= 0 && ki <= 10) {
                    const float w = gw(ki);
                    aU[j] = fmaf(w, hv.x, aU[j]);
                    aV[j] = fmaf(w, hv.y, aV[j]);
                    aP[j] = fmaf(w, hv.z, aP[j]);
                    aQ[j] = fmaf(w, hv.w, aQ[j]);
                }
            }
        }

        #pragma unroll
        for (int j = 0; j < 4; j++) {
            float A = aU[j] * aU[j];
            float B = aV[j] * aV[j];
            float P = aP[j], Q = aQ[j];
            float num_l = 0.5f * (A - B) + C1F;
            float den_l = 0.5f * (A + B) + C1F;
            float num_c = 0.5f * ((P - Q) - (A - B)) + C2F;
            float den_c = 0.5f * ((P + Q) - (A + B)) + C2F;
            float cs = __fdividef(num_c, den_c);
            lssim += __fdividef(num_l, den_l) * cs;
            lcs   += cs;
        }

        #pragma unroll
        for (int o = 16; o > 0; o >>= 1) {
            lssim += __shfl_xor_sync(0xFFFFFFFFu, lssim, o);
            lcs   += __shfl_xor_sync(0xFFFFFFFFu, lcs,   o);
        }
        if (tx == 0) { red_s[t >> 5] = lssim; red_c[t >> 5] = lcs; }
    }
    __syncthreads();
    if (t == 0) {
        float S = 0.f, Cc = 0.f;
        #pragma unroll
        for (int i = 0; i < TH / 4; i++) { S += red_s[i]; Cc += red_c[i]; }
        atomicAdd(&g_sums[2 * level],     (double)S);
        atomicAdd(&g_sums[2 * level + 1], (double)Cc);
    }
}

__global__ void finalize_kernel(float* __restrict__ out)
{
    const double w[5] = {0.0448, 0.2856, 0.3001, 0.2363, 0.1333};
    double res = 1.0;
    #pragma unroll
    for (int l = 0; l < 5; l++) {
        int side = 512 >> l;
        double cnt = (double)NPLANES * side * side;
        double v = (l < 4) ? (g_sums[2 * l + 1] / cnt)
                           : (g_sums[2 * l] / cnt);
        res *= pow(v, w[l]);
    }
    out[0] = (float)res;
}

extern "C" void kernel_launch(void* const* d_in, const int* in_sizes, int n_in,
                              void* d_out, int out_size)
{
    const float* img1 = (const float*)d_in[0];
    const float* img2 = (const float*)d_in[1];
    float* out = (float*)d_out;

    float *scr1 = nullptr, *scr2 = nullptr;
    cudaGetSymbolAddress((void**)&scr1, g_scr1);
    cudaGetSymbolAddress((void**)&scr2, g_scr2);

    const float* a[5];
    const float* b[5];
    a[0] = img1;            b[0] = img2;
    a[1] = scr1 + OFF_L1;   b[1] = scr2 + OFF_L1;
    a[2] = scr1 + OFF_L2;   b[2] = scr2 + OFF_L2;
    a[3] = scr1 + OFF_L3;   b[3] = scr2 + OFF_L3;
    a[4] = scr1 + OFF_L4;   b[4] = scr2 + OFF_L4;

    // smem sizes: big = 74 rows, small = 42 rows
    const int smem_big   = 74 * INWP * sizeof(float2) + 74 * TW * sizeof(float4); // 64064
    const int smem_small = 42 * INWP * sizeof(float2) + 42 * TW * sizeof(float4); // 36384

    cudaFuncSetAttribute(ssim_level_kernel<64, 512, 3>,
                         cudaFuncAttributeMaxDynamicSharedMemorySize, smem_big);
    cudaFuncSetAttribute(ssim_level_kernel<32, 384, 4>,
                         cudaFuncAttributeMaxDynamicSharedMemorySize, smem_small);

    zero_sums_kernel<<<1, 32>>>();

    for (int l = 0; l < 5; l++) {
        int side = 512 >> l;
        float* n1 = (l < 4) ? (float*)a[l + 1] : nullptr;
        float* n2 = (l < 4) ? (float*)b[l + 1] : nullptr;
        if (side >= 128) {
            dim3 grd(side / TW, side / 64, NPLANES);
            ssim_level_kernel<64, 512, 3><<<grd, 512, smem_big>>>(
                a[l], b[l], n1, n2, side, side, l);
        } else {
            dim3 grd(side / TW, side / 32, NPLANES);
            ssim_level_kernel<32, 384, 4><<<grd, 384, smem_small>>>(
                a[l], b[l], n1, n2, side, side, l);
        }
    }
    finalize_kernel<<<1, 1>>>(out);
}